// round 1
// baseline (speedup 1.0000x reference)
#include <cuda_runtime.h>
#include <math.h>

// Problem constants
#define NROWS 2048      // B*N
#define DIM   1024      // D
#define MKEYS 32768     // M
#define TK    32        // top-k
#define NH    16        // heads
#define HDIM  64        // head dim

// ---------------- scratch (device globals; no allocs allowed) ----------------
__device__ float g_qfull[NROWS * DIM];   // q_proj output; reused as pre-LN out
__device__ float g_ctx[NROWS * DIM];     // attention context
__device__ float g_qm[NROWS];            // per-row mean of q_full
__device__ float g_c[MKEYS];             // c_m = sum(mk)/ (sqrtD * ||mk||)
__device__ int   g_sel[2][TK];           // [0]=top-k of c (qm>0), [1]=top-k of -c
__device__ float g_Kt[2][DIM * TK];      // projected keys, TRANSPOSED [o][k]
__device__ float g_V[2][TK * DIM];       // projected values [k][o]

// ---------------- 1) per-memory-row stats: c_m ----------------
__global__ void stats_kernel(const float* __restrict__ keys) {
    int warp = (blockIdx.x * blockDim.x + threadIdx.x) >> 5;
    int lane = threadIdx.x & 31;
    if (warp >= MKEYS) return;
    const float4* p = (const float4*)(keys + (size_t)warp * DIM);
    float s = 0.f, sq = 0.f;
#pragma unroll
    for (int i = 0; i < 8; i++) {
        float4 v = p[lane + i * 32];
        s  += v.x + v.y + v.z + v.w;
        sq += v.x * v.x + v.y * v.y + v.z * v.z + v.w * v.w;
    }
#pragma unroll
    for (int o = 16; o; o >>= 1) {
        s  += __shfl_xor_sync(0xffffffffu, s, o);
        sq += __shfl_xor_sync(0xffffffffu, sq, o);
    }
    if (lane == 0) g_c[warp] = s / (32.0f * sqrtf(sq));  // sqrt(1024)=32
}

// ---------------- 2) two top-32 selections (iterative argmax, jax tie-break: lower idx) ----------------
__global__ void topk_kernel() {
    __shared__ unsigned char used[MKEYS];
    __shared__ float rv[1024];
    __shared__ int   ri[1024];
    int t = threadIdx.x;
    for (int s = 0; s < 2; s++) {
        for (int i = t; i < MKEYS; i += 1024) used[i] = 0;
        __syncthreads();
        float sgn = s ? -1.f : 1.f;
        for (int it = 0; it < TK; it++) {
            float bv = -INFINITY; int bi = MKEYS;
            for (int m = t; m < MKEYS; m += 1024) {
                if (used[m]) continue;
                float v = sgn * g_c[m];
                if (v > bv || (v == bv && m < bi)) { bv = v; bi = m; }
            }
            rv[t] = bv; ri[t] = bi;
            __syncthreads();
            for (int off = 512; off; off >>= 1) {
                if (t < off) {
                    float ov = rv[t + off]; int oi = ri[t + off];
                    if (ov > rv[t] || (ov == rv[t] && oi < ri[t])) { rv[t] = ov; ri[t] = oi; }
                }
                __syncthreads();
            }
            if (t == 0) { g_sel[s][it] = ri[0]; used[ri[0]] = 1; }
            __syncthreads();
        }
        __syncthreads();
    }
}

// ---------------- 3) fp32 NT GEMM: C[M,N] = A[M,K] * B[N,K]^T (+bias) ----------------
// 128x128 tile, BK=8, 256 threads, 8x8 per thread
__global__ void __launch_bounds__(256) gemm_nt(const float* __restrict__ A,
                                               const float* __restrict__ B,
                                               float* __restrict__ C,
                                               const float* __restrict__ bias,
                                               int Kdim, int Ndim) {
    __shared__ float As[8][132];
    __shared__ float Bs[8][132];
    int tid = threadIdx.x;
    int bm = blockIdx.y * 128, bn = blockIdx.x * 128;
    int lr = tid >> 1;
    int lc = (tid & 1) * 4;
    const float* Ap = A + (size_t)(bm + lr) * Kdim + lc;
    const float* Bp = B + (size_t)(bn + lr) * Kdim + lc;
    int tx = tid & 15, ty = tid >> 4;
    float acc[8][8];
#pragma unroll
    for (int i = 0; i < 8; i++)
#pragma unroll
        for (int j = 0; j < 8; j++) acc[i][j] = 0.f;

    for (int k0 = 0; k0 < Kdim; k0 += 8) {
        float4 a4 = *(const float4*)(Ap + k0);
        float4 b4 = *(const float4*)(Bp + k0);
        As[lc + 0][lr] = a4.x; As[lc + 1][lr] = a4.y; As[lc + 2][lr] = a4.z; As[lc + 3][lr] = a4.w;
        Bs[lc + 0][lr] = b4.x; Bs[lc + 1][lr] = b4.y; Bs[lc + 2][lr] = b4.z; Bs[lc + 3][lr] = b4.w;
        __syncthreads();
#pragma unroll
        for (int kk = 0; kk < 8; kk++) {
            float4 a0 = *(const float4*)&As[kk][ty * 8];
            float4 a1 = *(const float4*)&As[kk][ty * 8 + 4];
            float4 b0 = *(const float4*)&Bs[kk][tx * 8];
            float4 b1 = *(const float4*)&Bs[kk][tx * 8 + 4];
            float a[8] = {a0.x, a0.y, a0.z, a0.w, a1.x, a1.y, a1.z, a1.w};
            float b[8] = {b0.x, b0.y, b0.z, b0.w, b1.x, b1.y, b1.z, b1.w};
#pragma unroll
            for (int i = 0; i < 8; i++)
#pragma unroll
                for (int j = 0; j < 8; j++) acc[i][j] += a[i] * b[j];
        }
        __syncthreads();
    }
#pragma unroll
    for (int i = 0; i < 8; i++) {
        int row = bm + ty * 8 + i;
        float* Cp = C + (size_t)row * Ndim + bn + tx * 8;
#pragma unroll
        for (int j = 0; j < 8; j++) {
            float v = acc[i][j];
            if (bias) v += bias[bn + tx * 8 + j];
            Cp[j] = v;
        }
    }
}

// ---------------- 4) qm = row-mean of q_full ----------------
__global__ void qm_kernel() {
    __shared__ double sm[256];
    int row = blockIdx.x;
    const float* p = g_qfull + (size_t)row * DIM;
    double s = 0.0;
    for (int i = threadIdx.x; i < DIM; i += 256) s += (double)p[i];
    sm[threadIdx.x] = s;
    __syncthreads();
    for (int off = 128; off; off >>= 1) {
        if (threadIdx.x < off) sm[threadIdx.x] += sm[threadIdx.x + off];
        __syncthreads();
    }
    if (threadIdx.x == 0) g_qm[row] = (float)(sm[0] / DIM);
}

// ---------------- 5) project selected K/V: [32,1024] x [1024,1024]^T, x4 ----------------
// grid.x = o-tile (16 tiles of 64), grid.y in 0..3: set = y>>1, kv = y&1
__global__ void __launch_bounds__(256) selproj_kernel(const float* __restrict__ keys,
                                                      const float* __restrict__ vals,
                                                      const float* __restrict__ Wk,
                                                      const float* __restrict__ Wv) {
    int set = blockIdx.y >> 1, kv = blockIdx.y & 1;
    const float* S = kv ? vals : keys;
    const float* W = kv ? Wv : Wk;
    __shared__ float Ss[32][33];
    __shared__ float Ws[64][33];
    __shared__ int sel[32];
    int t = threadIdx.x;
    if (t < 32) sel[t] = g_sel[set][t];
    __syncthreads();
    int olocal = t & 63;
    int kbase = (t >> 6) * 8;
    int obase = blockIdx.x * 64;
    float acc[8];
#pragma unroll
    for (int i = 0; i < 8; i++) acc[i] = 0.f;

    for (int dc = 0; dc < DIM; dc += 32) {
        {   // gather source rows chunk [32][32]
            int idx = t * 4; int r = idx >> 5; int c = idx & 31;
            float4 v = *(const float4*)(S + (size_t)sel[r] * DIM + dc + c);
            Ss[r][c] = v.x; Ss[r][c + 1] = v.y; Ss[r][c + 2] = v.z; Ss[r][c + 3] = v.w;
        }
        {   // W chunk [64][32]
#pragma unroll
            for (int u = 0; u < 2; u++) {
                int id = t * 8 + u * 4; int r = id >> 5; int c = id & 31;
                float4 v = *(const float4*)(W + (size_t)(obase + r) * DIM + dc + c);
                Ws[r][c] = v.x; Ws[r][c + 1] = v.y; Ws[r][c + 2] = v.z; Ws[r][c + 3] = v.w;
            }
        }
        __syncthreads();
#pragma unroll
        for (int dd = 0; dd < 32; dd++) {
            float w = Ws[olocal][dd];
#pragma unroll
            for (int kk = 0; kk < 8; kk++) acc[kk] += Ss[kbase + kk][dd] * w;
        }
        __syncthreads();
    }
#pragma unroll
    for (int kk = 0; kk < 8; kk++) {
        int k = kbase + kk, o = obase + olocal;
        if (kv == 0) g_Kt[set][(size_t)o * TK + k] = acc[kk];   // transposed for coalesced score reads
        else         g_V[set][(size_t)k * DIM + o] = acc[kk];
    }
}

// ---------------- 6) per-row attention over 32 selected slots ----------------
// 512 threads = 16 warps; warp h, lane k
__global__ void __launch_bounds__(512) attn_kernel(float* __restrict__ out_avg,
                                                   float* __restrict__ out_sel) {
    int row = blockIdx.x;
    __shared__ float qs[DIM];
    __shared__ float att[NH][33];
    int t = threadIdx.x;
    const float* qp = g_qfull + (size_t)row * DIM;
    if (t < 256) ((float4*)qs)[t] = ((const float4*)qp)[t];
    int set = (g_qm[row] >= 0.f) ? 0 : 1;
    __syncthreads();

    int h = t >> 5, k = t & 31;
    const float* Ktp = g_Kt[set];
    const float* Vp  = g_V[set];
    const float* qh = qs + h * HDIM;
    float sc = 0.f;
#pragma unroll
    for (int j = 0; j < HDIM; j++) sc += qh[j] * Ktp[(size_t)(h * HDIM + j) * TK + k];
    sc *= 0.125f;  // 1/sqrt(64)
    float mx = sc;
#pragma unroll
    for (int o = 16; o; o >>= 1) mx = fmaxf(mx, __shfl_xor_sync(0xffffffffu, mx, o));
    float e = expf(sc - mx);
    float sum = e;
#pragma unroll
    for (int o = 16; o; o >>= 1) sum += __shfl_xor_sync(0xffffffffu, sum, o);
    float a = e / sum;
    att[h][k] = a;
    __syncthreads();

    if (h == 0) {
        float s2 = 0.f;
#pragma unroll
        for (int hh = 0; hh < NH; hh++) s2 += att[hh][k];
        out_avg[(size_t)row * TK + k] = s2 * (1.f / NH);
        out_sel[(size_t)row * TK + k] = (float)g_sel[set][k];
    }
#pragma unroll
    for (int u = 0; u < 2; u++) {
        int o = t + u * 512;
        int hh = o >> 6;
        float c = 0.f;
#pragma unroll
        for (int kk = 0; kk < TK; kk++) c += att[hh][kk] * Vp[(size_t)kk * DIM + o];
        g_ctx[(size_t)row * DIM + o] = c;
    }
}

// ---------------- 7) LayerNorm ----------------
__global__ void __launch_bounds__(256) ln_kernel(const float* __restrict__ X,
                                                 const float* __restrict__ gamma,
                                                 const float* __restrict__ beta,
                                                 float* __restrict__ out) {
    int row = blockIdx.x;
    __shared__ float red[256];
    int t = threadIdx.x;
    const float* p = X + (size_t)row * DIM;
    float4 v = ((const float4*)p)[t];
    float s = v.x + v.y + v.z + v.w;
    red[t] = s; __syncthreads();
    for (int off = 128; off; off >>= 1) { if (t < off) red[t] += red[t + off]; __syncthreads(); }
    float mu = red[0] * (1.f / DIM);
    __syncthreads();
    float d0 = v.x - mu, d1 = v.y - mu, d2 = v.z - mu, d3 = v.w - mu;
    red[t] = d0 * d0 + d1 * d1 + d2 * d2 + d3 * d3;
    __syncthreads();
    for (int off = 128; off; off >>= 1) { if (t < off) red[t] += red[t + off]; __syncthreads(); }
    float inv = rsqrtf(red[0] * (1.f / DIM) + 1e-5f);
    float4 g = ((const float4*)gamma)[t];
    float4 b = ((const float4*)beta)[t];
    float4 o;
    o.x = d0 * inv * g.x + b.x;
    o.y = d1 * inv * g.y + b.y;
    o.z = d2 * inv * g.z + b.z;
    o.w = d3 * inv * g.w + b.w;
    ((float4*)(out + (size_t)row * DIM))[t] = o;
}

// ---------------- launch ----------------
extern "C" void kernel_launch(void* const* d_in, const int* in_sizes, int n_in,
                              void* d_out, int out_size) {
    const float* q    = (const float*)d_in[0];
    const float* mk   = (const float*)d_in[1];
    const float* mv   = (const float*)d_in[2];
    const float* Wq   = (const float*)d_in[3];
    const float* Wk   = (const float*)d_in[4];
    const float* Wv   = (const float*)d_in[5];
    const float* Wo   = (const float*)d_in[6];
    const float* bo   = (const float*)d_in[7];
    const float* gamma = (const float*)d_in[8];
    const float* beta  = (const float*)d_in[9];
    float* out = (float*)d_out;

    float *p_qfull = nullptr, *p_ctx = nullptr;
    cudaGetSymbolAddress((void**)&p_qfull, g_qfull);
    cudaGetSymbolAddress((void**)&p_ctx, g_ctx);

    // output layout: [out 2048*1024 | avg_attn 2048*32 | sel_idx 2048*32]
    float* out_main = out;
    float* out_avg  = out + (size_t)NROWS * DIM;
    float* out_sel  = out + (size_t)NROWS * DIM + (size_t)NROWS * TK;

    // 1) memory-key stats (independent of everything else)
    stats_kernel<<<MKEYS / 8, 256>>>(mk);
    // 2) q_full = q @ Wq^T
    dim3 gq(DIM / 128, NROWS / 128);
    gemm_nt<<<gq, 256>>>(q, Wq, p_qfull, nullptr, DIM, DIM);
    // 3) qm
    qm_kernel<<<NROWS, 256>>>();
    // 4) two top-32 selections
    topk_kernel<<<1, 1024>>>();
    // 5) project selected K/V (4 small GEMMs)
    selproj_kernel<<<dim3(DIM / 64, 4), 256>>>(mk, mv, Wk, Wv);
    // 6) attention per row (also writes avg_attn + sel_idx outputs)
    attn_kernel<<<NROWS, 512>>>(out_avg, out_sel);
    // 7) out-projection GEMM (+bias), reusing g_qfull as scratch
    gemm_nt<<<gq, 256>>>(p_ctx, Wo, p_qfull, bo, DIM, DIM);
    // 8) LayerNorm -> final output
    ln_kernel<<<NROWS, 256>>>(p_qfull, gamma, beta, out_main);
    (void)in_sizes; (void)n_in; (void)out_size;
}

// round 2
// speedup vs baseline: 1.6990x; 1.6990x over previous
#include <cuda_runtime.h>
#include <math.h>

// Problem constants
#define NROWS 2048      // B*N
#define DIM   1024      // D
#define MKEYS 32768     // M
#define TK    32        // top-k
#define NH    16        // heads
#define HDIM  64        // head dim

// ---------------- scratch (device globals; no allocs allowed) ----------------
__device__ float g_qfull[NROWS * DIM];   // q_proj output; reused as pre-LN out
__device__ float g_ctx[NROWS * DIM];     // attention context
__device__ float g_qm[NROWS];            // per-row mean of q_full
__device__ float g_c[MKEYS];             // c_m = sum(mk)/ (sqrtD * ||mk||)
__device__ int   g_sel[2][TK];           // [0]=top-k of c (qm>0), [1]=top-k of -c
__device__ float g_Kt[2][DIM * TK];      // projected keys, TRANSPOSED [o][k]
__device__ float g_V[2][TK * DIM];       // projected values [k][o]

// ---------------- 1) per-memory-row stats: c_m ----------------
__global__ void stats_kernel(const float* __restrict__ keys) {
    int warp = (blockIdx.x * blockDim.x + threadIdx.x) >> 5;
    int lane = threadIdx.x & 31;
    if (warp >= MKEYS) return;
    const float4* p = (const float4*)(keys + (size_t)warp * DIM);
    float s = 0.f, sq = 0.f;
#pragma unroll
    for (int i = 0; i < 8; i++) {
        float4 v = p[lane + i * 32];
        s  += v.x + v.y + v.z + v.w;
        sq += v.x * v.x + v.y * v.y + v.z * v.z + v.w * v.w;
    }
#pragma unroll
    for (int o = 16; o; o >>= 1) {
        s  += __shfl_xor_sync(0xffffffffu, s, o);
        sq += __shfl_xor_sync(0xffffffffu, sq, o);
    }
    if (lane == 0) g_c[warp] = s / (32.0f * sqrtf(sq));  // sqrt(1024)=32
}

// ---------------- 2) warp-bitonic top-32 (two sets in parallel blocks) ----------------
__device__ __forceinline__ unsigned long long tk_make_key(float f, int m) {
    unsigned b = __float_as_uint(f);
    unsigned k = (b & 0x80000000u) ? ~b : (b | 0x80000000u);   // monotonic float->uint
    return ((unsigned long long)k << 32) | (unsigned long long)(0xFFFFFFFFu - (unsigned)m);
}

// full bitonic sort across the warp, ascending by lane (lane 0 = smallest)
__device__ __forceinline__ unsigned long long tk_sort_asc(unsigned long long v) {
    unsigned lane = threadIdx.x & 31;
#pragma unroll
    for (int k = 2; k <= 32; k <<= 1) {
#pragma unroll
        for (int j = k >> 1; j > 0; j >>= 1) {
            unsigned long long o = __shfl_xor_sync(0xffffffffu, v, j);
            bool up    = ((lane & k) == 0);
            bool lower = ((lane & j) == 0);
            unsigned long long mn = v < o ? v : o;
            unsigned long long mx = v < o ? o : v;
            v = (up == lower) ? mn : mx;
        }
    }
    return v;
}

// cleanup of a bitonic sequence to ascending order
__device__ __forceinline__ unsigned long long tk_bmerge_asc(unsigned long long v) {
    unsigned lane = threadIdx.x & 31;
#pragma unroll
    for (int j = 16; j > 0; j >>= 1) {
        unsigned long long o = __shfl_xor_sync(0xffffffffu, v, j);
        unsigned long long mn = v < o ? v : o;
        unsigned long long mx = v < o ? o : v;
        v = ((lane & j) == 0) ? mn : mx;
    }
    return v;
}

__global__ void __launch_bounds__(1024) topk_kernel() {
    int set = blockIdx.x;
    int lane = threadIdx.x & 31;
    int w = threadIdx.x >> 5;            // 0..31
    __shared__ unsigned long long sh[32][33];
    const float sgn = set ? -1.f : 1.f;
    int base = w * 1024;

    // init buffer with first chunk, sorted ascending
    unsigned long long buf = tk_make_key(sgn * g_c[base + lane], base + lane);
    buf = tk_sort_asc(buf);
#pragma unroll 1
    for (int c = 1; c < 32; c++) {
        int m = base + c * 32 + lane;
        unsigned long long k = tk_make_key(sgn * g_c[m], m);
        unsigned long long bmin = __shfl_sync(0xffffffffu, buf, 0);
        if (__any_sync(0xffffffffu, k > bmin)) {
            k = tk_sort_asc(k);
            unsigned long long o = __shfl_sync(0xffffffffu, k, 31 - lane); // descending view
            unsigned long long v = buf > o ? buf : o;  // top-32 of union (bitonic)
            buf = tk_bmerge_asc(v);
        }
    }
    sh[w][lane] = buf;
    __syncthreads();

    // tree merge 32 sorted lists -> sh[0]
#pragma unroll
    for (int st = 1; st < 32; st <<= 1) {
        if (w < 32 / (2 * st)) {
            unsigned long long A = sh[2 * w * st][lane];
            unsigned long long B = sh[(2 * w + 1) * st][31 - lane];
            unsigned long long v = A > B ? A : B;
            v = tk_bmerge_asc(v);
            sh[2 * w * st][lane] = v;
        }
        __syncthreads();
    }
    if (w == 0) {
        unsigned long long v = sh[0][lane];
        int m = (int)(0xFFFFFFFFu - (unsigned)(v & 0xFFFFFFFFull));
        g_sel[set][31 - lane] = m;   // descending by value, ties -> lower index first
    }
}

// ---------------- 3) fp32 NT GEMM: C[M,N] = A[M,K] * B[N,K]^T (+bias) ----------------
// 128x128 tile, BK=8, 256 threads, 8x8 per thread, register prefetch of next k-tile
__global__ void __launch_bounds__(256) gemm_nt(const float* __restrict__ A,
                                               const float* __restrict__ B,
                                               float* __restrict__ C,
                                               const float* __restrict__ bias,
                                               int Kdim, int Ndim) {
    __shared__ float As[8][132];
    __shared__ float Bs[8][132];
    int tid = threadIdx.x;
    int bm = blockIdx.y * 128, bn = blockIdx.x * 128;
    int lr = tid >> 1;
    int lc = (tid & 1) * 4;
    const float* Ap = A + (size_t)(bm + lr) * Kdim + lc;
    const float* Bp = B + (size_t)(bn + lr) * Kdim + lc;
    int tx = tid & 15, ty = tid >> 4;
    float acc[8][8];
#pragma unroll
    for (int i = 0; i < 8; i++)
#pragma unroll
        for (int j = 0; j < 8; j++) acc[i][j] = 0.f;

    float4 a4 = *(const float4*)(Ap);
    float4 b4 = *(const float4*)(Bp);

    for (int k0 = 0; k0 < Kdim; k0 += 8) {
        As[lc + 0][lr] = a4.x; As[lc + 1][lr] = a4.y; As[lc + 2][lr] = a4.z; As[lc + 3][lr] = a4.w;
        Bs[lc + 0][lr] = b4.x; Bs[lc + 1][lr] = b4.y; Bs[lc + 2][lr] = b4.z; Bs[lc + 3][lr] = b4.w;
        __syncthreads();
        if (k0 + 8 < Kdim) {           // prefetch next tile during compute
            a4 = *(const float4*)(Ap + k0 + 8);
            b4 = *(const float4*)(Bp + k0 + 8);
        }
#pragma unroll
        for (int kk = 0; kk < 8; kk++) {
            float4 a0 = *(const float4*)&As[kk][ty * 8];
            float4 a1 = *(const float4*)&As[kk][ty * 8 + 4];
            float4 b0 = *(const float4*)&Bs[kk][tx * 8];
            float4 b1 = *(const float4*)&Bs[kk][tx * 8 + 4];
            float a[8] = {a0.x, a0.y, a0.z, a0.w, a1.x, a1.y, a1.z, a1.w};
            float b[8] = {b0.x, b0.y, b0.z, b0.w, b1.x, b1.y, b1.z, b1.w};
#pragma unroll
            for (int i = 0; i < 8; i++)
#pragma unroll
                for (int j = 0; j < 8; j++) acc[i][j] += a[i] * b[j];
        }
        __syncthreads();
    }
#pragma unroll
    for (int i = 0; i < 8; i++) {
        int row = bm + ty * 8 + i;
        float* Cp = C + (size_t)row * Ndim + bn + tx * 8;
#pragma unroll
        for (int j = 0; j < 8; j++) {
            float v = acc[i][j];
            if (bias) v += bias[bn + tx * 8 + j];
            Cp[j] = v;
        }
    }
}

// ---------------- 4) qm = row-mean of q_full ----------------
__global__ void qm_kernel() {
    __shared__ double sm[256];
    int row = blockIdx.x;
    const float* p = g_qfull + (size_t)row * DIM;
    double s = 0.0;
    for (int i = threadIdx.x; i < DIM; i += 256) s += (double)p[i];
    sm[threadIdx.x] = s;
    __syncthreads();
    for (int off = 128; off; off >>= 1) {
        if (threadIdx.x < off) sm[threadIdx.x] += sm[threadIdx.x + off];
        __syncthreads();
    }
    if (threadIdx.x == 0) g_qm[row] = (float)(sm[0] / DIM);
}

// ---------------- 5) project selected K/V: [32,1024] x [1024,1024]^T, x4 ----------------
__global__ void __launch_bounds__(256) selproj_kernel(const float* __restrict__ keys,
                                                      const float* __restrict__ vals,
                                                      const float* __restrict__ Wk,
                                                      const float* __restrict__ Wv) {
    int set = blockIdx.y >> 1, kv = blockIdx.y & 1;
    const float* S = kv ? vals : keys;
    const float* W = kv ? Wv : Wk;
    __shared__ float Ss[32][33];
    __shared__ float Ws[64][33];
    __shared__ int sel[32];
    int t = threadIdx.x;
    if (t < 32) sel[t] = g_sel[set][t];
    __syncthreads();
    int olocal = t & 63;
    int kbase = (t >> 6) * 8;
    int obase = blockIdx.x * 64;
    float acc[8];
#pragma unroll
    for (int i = 0; i < 8; i++) acc[i] = 0.f;

    for (int dc = 0; dc < DIM; dc += 32) {
        {   // gather source rows chunk [32][32]
            int idx = t * 4; int r = idx >> 5; int c = idx & 31;
            float4 v = *(const float4*)(S + (size_t)sel[r] * DIM + dc + c);
            Ss[r][c] = v.x; Ss[r][c + 1] = v.y; Ss[r][c + 2] = v.z; Ss[r][c + 3] = v.w;
        }
        {   // W chunk [64][32]
#pragma unroll
            for (int u = 0; u < 2; u++) {
                int id = t * 8 + u * 4; int r = id >> 5; int c = id & 31;
                float4 v = *(const float4*)(W + (size_t)(obase + r) * DIM + dc + c);
                Ws[r][c] = v.x; Ws[r][c + 1] = v.y; Ws[r][c + 2] = v.z; Ws[r][c + 3] = v.w;
            }
        }
        __syncthreads();
#pragma unroll
        for (int dd = 0; dd < 32; dd++) {
            float w = Ws[olocal][dd];
#pragma unroll
            for (int kk = 0; kk < 8; kk++) acc[kk] += Ss[kbase + kk][dd] * w;
        }
        __syncthreads();
    }
#pragma unroll
    for (int kk = 0; kk < 8; kk++) {
        int k = kbase + kk, o = obase + olocal;
        if (kv == 0) g_Kt[set][(size_t)o * TK + k] = acc[kk];   // transposed for coalesced score reads
        else         g_V[set][(size_t)k * DIM + o] = acc[kk];
    }
}

// ---------------- 6) per-row attention over 32 selected slots ----------------
__global__ void __launch_bounds__(512) attn_kernel(float* __restrict__ out_avg,
                                                   float* __restrict__ out_sel) {
    int row = blockIdx.x;
    __shared__ float qs[DIM];
    __shared__ float att[NH][33];
    int t = threadIdx.x;
    const float* qp = g_qfull + (size_t)row * DIM;
    if (t < 256) ((float4*)qs)[t] = ((const float4*)qp)[t];
    int set = (g_qm[row] >= 0.f) ? 0 : 1;
    __syncthreads();

    int h = t >> 5, k = t & 31;
    const float* Ktp = g_Kt[set];
    const float* Vp  = g_V[set];
    const float* qh = qs + h * HDIM;
    float sc = 0.f;
#pragma unroll
    for (int j = 0; j < HDIM; j++) sc += qh[j] * Ktp[(size_t)(h * HDIM + j) * TK + k];
    sc *= 0.125f;  // 1/sqrt(64)
    float mx = sc;
#pragma unroll
    for (int o = 16; o; o >>= 1) mx = fmaxf(mx, __shfl_xor_sync(0xffffffffu, mx, o));
    float e = expf(sc - mx);
    float sum = e;
#pragma unroll
    for (int o = 16; o; o >>= 1) sum += __shfl_xor_sync(0xffffffffu, sum, o);
    float a = e / sum;
    att[h][k] = a;
    __syncthreads();

    if (h == 0) {
        float s2 = 0.f;
#pragma unroll
        for (int hh = 0; hh < NH; hh++) s2 += att[hh][k];
        out_avg[(size_t)row * TK + k] = s2 * (1.f / NH);
        out_sel[(size_t)row * TK + k] = (float)g_sel[set][k];
    }
#pragma unroll
    for (int u = 0; u < 2; u++) {
        int o = t + u * 512;
        int hh = o >> 6;
        float c = 0.f;
#pragma unroll
        for (int kk = 0; kk < TK; kk++) c += att[hh][kk] * Vp[(size_t)kk * DIM + o];
        g_ctx[(size_t)row * DIM + o] = c;
    }
}

// ---------------- 7) LayerNorm ----------------
__global__ void __launch_bounds__(256) ln_kernel(const float* __restrict__ X,
                                                 const float* __restrict__ gamma,
                                                 const float* __restrict__ beta,
                                                 float* __restrict__ out) {
    int row = blockIdx.x;
    __shared__ float red[256];
    int t = threadIdx.x;
    const float* p = X + (size_t)row * DIM;
    float4 v = ((const float4*)p)[t];
    float s = v.x + v.y + v.z + v.w;
    red[t] = s; __syncthreads();
    for (int off = 128; off; off >>= 1) { if (t < off) red[t] += red[t + off]; __syncthreads(); }
    float mu = red[0] * (1.f / DIM);
    __syncthreads();
    float d0 = v.x - mu, d1 = v.y - mu, d2 = v.z - mu, d3 = v.w - mu;
    red[t] = d0 * d0 + d1 * d1 + d2 * d2 + d3 * d3;
    __syncthreads();
    for (int off = 128; off; off >>= 1) { if (t < off) red[t] += red[t + off]; __syncthreads(); }
    float inv = rsqrtf(red[0] * (1.f / DIM) + 1e-5f);
    float4 g = ((const float4*)gamma)[t];
    float4 b = ((const float4*)beta)[t];
    float4 o;
    o.x = d0 * inv * g.x + b.x;
    o.y = d1 * inv * g.y + b.y;
    o.z = d2 * inv * g.z + b.z;
    o.w = d3 * inv * g.w + b.w;
    ((float4*)(out + (size_t)row * DIM))[t] = o;
}

// ---------------- launch ----------------
extern "C" void kernel_launch(void* const* d_in, const int* in_sizes, int n_in,
                              void* d_out, int out_size) {
    const float* q    = (const float*)d_in[0];
    const float* mk   = (const float*)d_in[1];
    const float* mv   = (const float*)d_in[2];
    const float* Wq   = (const float*)d_in[3];
    const float* Wk   = (const float*)d_in[4];
    const float* Wv   = (const float*)d_in[5];
    const float* Wo   = (const float*)d_in[6];
    const float* bo   = (const float*)d_in[7];
    const float* gamma = (const float*)d_in[8];
    const float* beta  = (const float*)d_in[9];
    float* out = (float*)d_out;

    float *p_qfull = nullptr, *p_ctx = nullptr;
    cudaGetSymbolAddress((void**)&p_qfull, g_qfull);
    cudaGetSymbolAddress((void**)&p_ctx, g_ctx);

    // output layout: [out 2048*1024 | avg_attn 2048*32 | sel_idx 2048*32]
    float* out_main = out;
    float* out_avg  = out + (size_t)NROWS * DIM;
    float* out_sel  = out + (size_t)NROWS * DIM + (size_t)NROWS * TK;

    // 1) memory-key stats
    stats_kernel<<<MKEYS / 8, 256>>>(mk);
    // 2) q_full = q @ Wq^T
    dim3 gq(DIM / 128, NROWS / 128);
    gemm_nt<<<gq, 256>>>(q, Wq, p_qfull, nullptr, DIM, DIM);
    // 3) qm
    qm_kernel<<<NROWS, 256>>>();
    // 4) two top-32 selections (parallel blocks, warp-bitonic)
    topk_kernel<<<2, 1024>>>();
    // 5) project selected K/V (4 small GEMMs)
    selproj_kernel<<<dim3(DIM / 64, 4), 256>>>(mk, mv, Wk, Wv);
    // 6) attention per row (also writes avg_attn + sel_idx outputs)
    attn_kernel<<<NROWS, 512>>>(out_avg, out_sel);
    // 7) out-projection GEMM (+bias)
    gemm_nt<<<gq, 256>>>(p_ctx, Wo, p_qfull, bo, DIM, DIM);
    // 8) LayerNorm -> final output
    ln_kernel<<<NROWS, 256>>>(p_qfull, gamma, beta, out_main);
    (void)in_sizes; (void)n_in; (void)out_size;
}

// round 6
// speedup vs baseline: 3.0272x; 1.7818x over previous
#include <cuda_runtime.h>
#include <cuda_bf16.h>
#include <math.h>
#include <stdint.h>

// Problem constants
#define NROWS 2048      // B*N
#define DIM   1024      // D
#define MKEYS 32768     // M
#define TK    32        // top-k
#define NH    16        // heads
#define HDIM  64        // head dim

// ================= scratch (device globals) =================
__device__ float g_qfull[NROWS * DIM];   // q_proj output; reused as pre-LN out
__device__ float g_ctx[NROWS * DIM];     // attention context
__device__ int   g_set[NROWS];           // per-row set selector (sign of qm)
__device__ float g_c[MKEYS];             // c_m
__device__ int   g_sel[2][TK];
__device__ float g_Kt[2][DIM * TK];      // projected keys, transposed [o][k]
__device__ float g_V[2][TK * DIM];       // projected values [k][o]
__device__ float g_att[NROWS * (NH * TK)];
__device__ unsigned long long g_part[2][16][TK];
// bf16 split buffers
__device__ __nv_bfloat16 g_Ahi[NROWS * DIM], g_Alo[NROWS * DIM];
__device__ __nv_bfloat16 g_Wqhi[DIM * DIM], g_Wqlo[DIM * DIM];
__device__ __nv_bfloat16 g_Wohi[DIM * DIM], g_Wolo[DIM * DIM];

// ================= PTX helpers (sm_80+ features only) =================
__device__ __forceinline__ uint32_t smem_u32(const void* p) {
    uint32_t a;
    asm("{ .reg .u64 t; cvta.to.shared.u64 t, %1; cvt.u32.u64 %0, t; }" : "=r"(a) : "l"(p));
    return a;
}
__device__ __forceinline__ void ldsm4(uint32_t* r, uint32_t addr) {
    asm volatile("ldmatrix.sync.aligned.m8n8.x4.shared.b16 {%0,%1,%2,%3}, [%4];"
        : "=r"(r[0]), "=r"(r[1]), "=r"(r[2]), "=r"(r[3]) : "r"(addr));
}
__device__ __forceinline__ void mma16816(float* c, const uint32_t* a, const uint32_t* b) {
    asm volatile("mma.sync.aligned.m16n8k16.row.col.f32.bf16.bf16.f32 "
        "{%0,%1,%2,%3}, {%4,%5,%6,%7}, {%8,%9}, {%0,%1,%2,%3};"
        : "+f"(c[0]), "+f"(c[1]), "+f"(c[2]), "+f"(c[3])
        : "r"(a[0]), "r"(a[1]), "r"(a[2]), "r"(a[3]), "r"(b[0]), "r"(b[1]));
}

// ================= 1) per-memory-row stats =================
__global__ void stats_kernel(const float* __restrict__ keys) {
    int warp = (blockIdx.x * blockDim.x + threadIdx.x) >> 5;
    int lane = threadIdx.x & 31;
    if (warp >= MKEYS) return;
    const float4* p = (const float4*)(keys + (size_t)warp * DIM);
    float s = 0.f, sq = 0.f;
#pragma unroll
    for (int i = 0; i < 8; i++) {
        float4 v = p[lane + i * 32];
        s  += v.x + v.y + v.z + v.w;
        sq += v.x * v.x + v.y * v.y + v.z * v.z + v.w * v.w;
    }
#pragma unroll
    for (int o = 16; o; o >>= 1) {
        s  += __shfl_xor_sync(0xffffffffu, s, o);
        sq += __shfl_xor_sync(0xffffffffu, sq, o);
    }
    if (lane == 0) g_c[warp] = s / (32.0f * sqrtf(sq));
}

// ================= 2) top-32 =================
__device__ __forceinline__ unsigned long long tk_make_key(float f, int m) {
    unsigned b = __float_as_uint(f);
    unsigned k = (b & 0x80000000u) ? ~b : (b | 0x80000000u);
    return ((unsigned long long)k << 32) | (unsigned long long)(0xFFFFFFFFu - (unsigned)m);
}
__device__ __forceinline__ unsigned long long tk_sort_asc(unsigned long long v) {
    unsigned lane = threadIdx.x & 31;
#pragma unroll
    for (int k = 2; k <= 32; k <<= 1) {
#pragma unroll
        for (int j = k >> 1; j > 0; j >>= 1) {
            unsigned long long o = __shfl_xor_sync(0xffffffffu, v, j);
            bool up = ((lane & k) == 0), lower = ((lane & j) == 0);
            unsigned long long mn = v < o ? v : o, mx = v < o ? o : v;
            v = (up == lower) ? mn : mx;
        }
    }
    return v;
}
__device__ __forceinline__ unsigned long long tk_bmerge_asc(unsigned long long v) {
    unsigned lane = threadIdx.x & 31;
#pragma unroll
    for (int j = 16; j > 0; j >>= 1) {
        unsigned long long o = __shfl_xor_sync(0xffffffffu, v, j);
        unsigned long long mn = v < o ? v : o, mx = v < o ? o : v;
        v = ((lane & j) == 0) ? mn : mx;
    }
    return v;
}
__global__ void __launch_bounds__(1024) topk_part() {
    int set = blockIdx.y, p = blockIdx.x;
    int lane = threadIdx.x & 31, w = threadIdx.x >> 5;
    __shared__ unsigned long long sh[32][33];
    float sgn = set ? -1.f : 1.f;
    int base = p * 2048 + w * 64;
    int i0 = base + lane, i1 = base + 32 + lane;
    float f0 = sgn * g_c[i0], f1 = sgn * g_c[i1];
    unsigned long long a = tk_sort_asc(tk_make_key(f0, i0));
    unsigned long long b = tk_sort_asc(tk_make_key(f1, i1));
    unsigned long long o = __shfl_sync(0xffffffffu, b, 31 - lane);
    unsigned long long v = a > o ? a : o;
    a = tk_bmerge_asc(v);
    sh[w][lane] = a;
    __syncthreads();
#pragma unroll
    for (int st = 1; st < 32; st <<= 1) {
        if (w < 16 / st) {
            unsigned long long A = sh[2 * w * st][lane];
            unsigned long long B = sh[(2 * w + 1) * st][31 - lane];
            unsigned long long m = A > B ? A : B;
            m = tk_bmerge_asc(m);
            sh[2 * w * st][lane] = m;
        }
        __syncthreads();
    }
    if (w == 0) g_part[set][p][lane] = sh[0][lane];
}
__global__ void __launch_bounds__(512) topk_merge() {
    int set = blockIdx.x;
    int lane = threadIdx.x & 31, w = threadIdx.x >> 5;
    __shared__ unsigned long long sh[16][33];
    sh[w][lane] = g_part[set][w][lane];
    __syncthreads();
#pragma unroll
    for (int st = 1; st < 16; st <<= 1) {
        if (w < 8 / st) {
            unsigned long long A = sh[2 * w * st][lane];
            unsigned long long B = sh[(2 * w + 1) * st][31 - lane];
            unsigned long long m = A > B ? A : B;
            m = tk_bmerge_asc(m);
            sh[2 * w * st][lane] = m;
        }
        __syncthreads();
    }
    if (w == 0) {
        unsigned long long v = sh[0][lane];
        int m = (int)(0xFFFFFFFFu - (unsigned)(v & 0xFFFFFFFFull));
        g_sel[set][31 - lane] = m;
    }
}

// ================= 3) fp32 -> bf16 hi/lo split =================
__global__ void __launch_bounds__(256) conv_kernel(const float* __restrict__ X,
                                                   __nv_bfloat16* __restrict__ hi,
                                                   __nv_bfloat16* __restrict__ lo, int n4) {
    int i = blockIdx.x * blockDim.x + threadIdx.x;
    if (i >= n4) return;
    float4 v = ((const float4*)X)[i];
    __nv_bfloat16 h0 = __float2bfloat16(v.x), h1 = __float2bfloat16(v.y);
    __nv_bfloat16 h2 = __float2bfloat16(v.z), h3 = __float2bfloat16(v.w);
    __nv_bfloat16 l0 = __float2bfloat16(v.x - __bfloat162float(h0));
    __nv_bfloat16 l1 = __float2bfloat16(v.y - __bfloat162float(h1));
    __nv_bfloat16 l2 = __float2bfloat16(v.z - __bfloat162float(h2));
    __nv_bfloat16 l3 = __float2bfloat16(v.w - __bfloat162float(h3));
    ((__nv_bfloat162*)hi)[2 * i]     = __halves2bfloat162(h0, h1);
    ((__nv_bfloat162*)hi)[2 * i + 1] = __halves2bfloat162(h2, h3);
    ((__nv_bfloat162*)lo)[2 * i]     = __halves2bfloat162(l0, l1);
    ((__nv_bfloat162*)lo)[2 * i + 1] = __halves2bfloat162(l2, l3);
}

// ================= 4) HMMA bf16x3 GEMM: C[2048,1024] = A*B^T (+bias) =================
// 128x128 CTA tile, BK=32, 8 warps (2x4), warp tile 64x32
#define BK 32
#define NK (DIM / BK)
#define SSTRIDE 40   // bf16 elems per smem row (80B; conflict-free ldmatrix)

__global__ void __launch_bounds__(256) mma_gemm(
    const __nv_bfloat16* __restrict__ Ahi, const __nv_bfloat16* __restrict__ Alo,
    const __nv_bfloat16* __restrict__ Bhi, const __nv_bfloat16* __restrict__ Blo,
    float* __restrict__ C, const float* __restrict__ bias) {
    __shared__ __align__(16) __nv_bfloat16 sm[4][128 * SSTRIDE];
    int tid = threadIdx.x, lane = tid & 31, wid = tid >> 5;
    int bm = blockIdx.y * 128, bn = blockIdx.x * 128;
    int wm = wid >> 2, wn = wid & 3;
    int m0 = wm * 64, n0 = wn * 32;

    const __nv_bfloat16* srcs[4] = {
        Ahi + (size_t)bm * DIM, Alo + (size_t)bm * DIM,
        Bhi + (size_t)bn * DIM, Blo + (size_t)bn * DIM };

    uint32_t sbase[4];
#pragma unroll
    for (int t = 0; t < 4; t++) sbase[t] = smem_u32(sm[t]);

    // ldmatrix per-thread address components
    int a_ro = (m0 + (lane & 15)) * SSTRIDE + ((lane & 16) ? 8 : 0);
    int b_ro = (n0 + (lane & 7) + ((lane & 16) ? 8 : 0)) * SSTRIDE + ((lane & 8) ? 8 : 0);

    float acc[4][4][4];
#pragma unroll
    for (int i = 0; i < 4; i++)
#pragma unroll
        for (int j = 0; j < 4; j++)
#pragma unroll
            for (int r = 0; r < 4; r++) acc[i][j][r] = 0.f;

    int row_g = tid >> 2;                  // 0..63? no: tid>>2 in 0..63 for c per-u
    // global load assignment: c = tid + u*256, row = c>>2 (0..127), inner = (c&3)*8
    uint4 pf[8];
#pragma unroll
    for (int t = 0; t < 4; t++)
#pragma unroll
        for (int u = 0; u < 2; u++) {
            int c = tid + u * 256, row = c >> 2, inner = (c & 3) * 8;
            pf[t * 2 + u] = *(const uint4*)(srcs[t] + (size_t)row * DIM + inner);
        }
    (void)row_g;

#pragma unroll 1
    for (int kt = 0; kt < NK; kt++) {
#pragma unroll
        for (int t = 0; t < 4; t++)
#pragma unroll
            for (int u = 0; u < 2; u++) {
                int c = tid + u * 256, row = c >> 2, inner = (c & 3) * 8;
                *(uint4*)(&sm[t][row * SSTRIDE + inner]) = pf[t * 2 + u];
            }
        __syncthreads();
        if (kt + 1 < NK) {
#pragma unroll
            for (int t = 0; t < 4; t++)
#pragma unroll
                for (int u = 0; u < 2; u++) {
                    int c = tid + u * 256, row = c >> 2, inner = (c & 3) * 8;
                    pf[t * 2 + u] = *(const uint4*)(srcs[t] + (size_t)row * DIM + (kt + 1) * BK + inner);
                }
        }
#pragma unroll
        for (int ks = 0; ks < 2; ks++) {
            uint32_t ah[4][4], al[4][4];
#pragma unroll
            for (int mt = 0; mt < 4; mt++) {
                uint32_t off = 2u * (uint32_t)(a_ro + mt * 16 * SSTRIDE + ks * 16);
                ldsm4(ah[mt], sbase[0] + off);
                ldsm4(al[mt], sbase[1] + off);
            }
            uint32_t bh[4][2], bl[4][2];
#pragma unroll
            for (int pr = 0; pr < 2; pr++) {
                uint32_t off = 2u * (uint32_t)(b_ro + pr * 16 * SSTRIDE + ks * 16);
                uint32_t r[4];
                ldsm4(r, sbase[2] + off);
                bh[pr * 2][0] = r[0]; bh[pr * 2][1] = r[1];
                bh[pr * 2 + 1][0] = r[2]; bh[pr * 2 + 1][1] = r[3];
                ldsm4(r, sbase[3] + off);
                bl[pr * 2][0] = r[0]; bl[pr * 2][1] = r[1];
                bl[pr * 2 + 1][0] = r[2]; bl[pr * 2 + 1][1] = r[3];
            }
#pragma unroll
            for (int mt = 0; mt < 4; mt++)
#pragma unroll
                for (int nt = 0; nt < 4; nt++) {
                    mma16816(acc[mt][nt], ah[mt], bh[nt]);
                    mma16816(acc[mt][nt], ah[mt], bl[nt]);
                    mma16816(acc[mt][nt], al[mt], bh[nt]);
                }
        }
        __syncthreads();
    }

    int gid = lane >> 2, tig = lane & 3;
#pragma unroll
    for (int mt = 0; mt < 4; mt++)
#pragma unroll
        for (int nt = 0; nt < 4; nt++) {
            int row = bm + m0 + mt * 16 + gid;
            int col = bn + n0 + nt * 8 + tig * 2;
            float b0 = 0.f, b1 = 0.f;
            if (bias) { b0 = bias[col]; b1 = bias[col + 1]; }
            float2 v0 = make_float2(acc[mt][nt][0] + b0, acc[mt][nt][1] + b1);
            float2 v1 = make_float2(acc[mt][nt][2] + b0, acc[mt][nt][3] + b1);
            *(float2*)(C + (size_t)row * DIM + col) = v0;
            *(float2*)(C + (size_t)(row + 8) * DIM + col) = v1;
        }
}

// ================= 5) qm sign -> set =================
__global__ void qm_kernel() {
    __shared__ double sm[256];
    int row = blockIdx.x;
    const float* p = g_qfull + (size_t)row * DIM;
    double s = 0.0;
    for (int i = threadIdx.x; i < DIM; i += 256) s += (double)p[i];
    sm[threadIdx.x] = s;
    __syncthreads();
    for (int off = 128; off; off >>= 1) {
        if (threadIdx.x < off) sm[threadIdx.x] += sm[threadIdx.x + off];
        __syncthreads();
    }
    if (threadIdx.x == 0) g_set[row] = (sm[0] >= 0.0) ? 0 : 1;
}

// ================= 6) project selected K/V =================
__global__ void __launch_bounds__(256) selproj_kernel(const float* __restrict__ keys,
                                                      const float* __restrict__ vals,
                                                      const float* __restrict__ Wk,
                                                      const float* __restrict__ Wv) {
    int set = blockIdx.y >> 1, kv = blockIdx.y & 1;
    const float* S = kv ? vals : keys;
    const float* W = kv ? Wv : Wk;
    __shared__ float Ss[32][33];
    __shared__ float Ws[64][33];
    __shared__ int sel[32];
    int t = threadIdx.x;
    if (t < 32) sel[t] = g_sel[set][t];
    __syncthreads();
    int olocal = t & 63;
    int kbase = (t >> 6) * 8;
    int obase = blockIdx.x * 64;
    float acc[8];
#pragma unroll
    for (int i = 0; i < 8; i++) acc[i] = 0.f;

    for (int dc = 0; dc < DIM; dc += 32) {
        {
            int idx = t * 4; int r = idx >> 5; int c = idx & 31;
            float4 v = *(const float4*)(S + (size_t)sel[r] * DIM + dc + c);
            Ss[r][c] = v.x; Ss[r][c + 1] = v.y; Ss[r][c + 2] = v.z; Ss[r][c + 3] = v.w;
        }
        {
#pragma unroll
            for (int u = 0; u < 2; u++) {
                int id = t * 8 + u * 4; int r = id >> 5; int c = id & 31;
                float4 v = *(const float4*)(W + (size_t)(obase + r) * DIM + dc + c);
                Ws[r][c] = v.x; Ws[r][c + 1] = v.y; Ws[r][c + 2] = v.z; Ws[r][c + 3] = v.w;
            }
        }
        __syncthreads();
#pragma unroll
        for (int dd = 0; dd < 32; dd++) {
            float w = Ws[olocal][dd];
#pragma unroll
            for (int kk = 0; kk < 8; kk++) acc[kk] += Ss[kbase + kk][dd] * w;
        }
        __syncthreads();
    }
#pragma unroll
    for (int kk = 0; kk < 8; kk++) {
        int k = kbase + kk, o = obase + olocal;
        if (kv == 0) g_Kt[set][(size_t)o * TK + k] = acc[kk];
        else         g_V[set][(size_t)k * DIM + o] = acc[kk];
    }
}

// ================= 7a) attention scores + softmax =================
__global__ void __launch_bounds__(256) attn_scores() {
    int h = blockIdx.x;
    int r0 = blockIdx.y * 64;
    __shared__ float qs[64][65];
    __shared__ float Ks[2][64][33];
    __shared__ int sets[64];
    int tid = threadIdx.x;
#pragma unroll
    for (int u = 0; u < 4; u++) {
        int c = tid + u * 256;
        int r = c >> 4, q4 = c & 15;
        float4 v = *(const float4*)(g_qfull + (size_t)(r0 + r) * DIM + h * HDIM + q4 * 4);
        qs[r][q4 * 4 + 0] = v.x; qs[r][q4 * 4 + 1] = v.y; qs[r][q4 * 4 + 2] = v.z; qs[r][q4 * 4 + 3] = v.w;
    }
#pragma unroll
    for (int u = 0; u < 4; u++) {
        int c = tid + u * 256;
        int s = c >> 9, rem = c & 511, j = rem >> 3, k4 = rem & 7;
        float4 v = *(const float4*)(&g_Kt[s][(size_t)(h * HDIM + j) * TK + k4 * 4]);
        Ks[s][j][k4 * 4 + 0] = v.x; Ks[s][j][k4 * 4 + 1] = v.y; Ks[s][j][k4 * 4 + 2] = v.z; Ks[s][j][k4 * 4 + 3] = v.w;
    }
    if (tid < 64) sets[tid] = g_set[r0 + tid];
    __syncthreads();
    int r = tid >> 2, kg = tid & 3;
    int s = sets[r];
    float sc[8];
#pragma unroll
    for (int kk = 0; kk < 8; kk++) sc[kk] = 0.f;
#pragma unroll
    for (int j = 0; j < 64; j++) {
        float qv = qs[r][j];
#pragma unroll
        for (int kk = 0; kk < 8; kk++) sc[kk] += qv * Ks[s][j][kg * 8 + kk];
    }
    float mx = -INFINITY;
#pragma unroll
    for (int kk = 0; kk < 8; kk++) { sc[kk] *= 0.125f; mx = fmaxf(mx, sc[kk]); }
#pragma unroll
    for (int o = 1; o <= 2; o <<= 1) mx = fmaxf(mx, __shfl_xor_sync(0xffffffffu, mx, o));
    float e[8]; float sum = 0.f;
#pragma unroll
    for (int kk = 0; kk < 8; kk++) { e[kk] = expf(sc[kk] - mx); sum += e[kk]; }
#pragma unroll
    for (int o = 1; o <= 2; o <<= 1) sum += __shfl_xor_sync(0xffffffffu, sum, o);
    float inv = 1.f / sum;
    float* dst = &g_att[(size_t)(r0 + r) * (NH * TK) + h * TK + kg * 8];
    *(float4*)(dst)     = make_float4(e[0] * inv, e[1] * inv, e[2] * inv, e[3] * inv);
    *(float4*)(dst + 4) = make_float4(e[4] * inv, e[5] * inv, e[6] * inv, e[7] * inv);
}

// ================= 7b) context + avg_attn + sel_idx =================
__global__ void __launch_bounds__(256) attn_ctx(float* __restrict__ out_avg,
                                                float* __restrict__ out_sel) {
    int r0 = blockIdx.x * 16;
    __shared__ float att[16][NH * 33];
    __shared__ int sets[16];
    int tid = threadIdx.x;
    if (tid < 16) sets[tid] = g_set[r0 + tid];
#pragma unroll
    for (int u = 0; u < 8; u++) {
        int c = tid + u * 256;
        int r = c >> 7, rem = c & 127;
        float4 v = *(const float4*)(&g_att[(size_t)(r0 + r) * (NH * TK) + rem * 4]);
        int hh = (rem * 4) >> 5, k = (rem * 4) & 31;
        float* d = &att[r][hh * 33 + k];
        d[0] = v.x; d[1] = v.y; d[2] = v.z; d[3] = v.w;
    }
    __syncthreads();
#pragma unroll
    for (int u = 0; u < 2; u++) {
        int c = tid + u * 256;
        int r = c >> 5, k = c & 31;
        float sm = 0.f;
#pragma unroll
        for (int hh = 0; hh < NH; hh++) sm += att[r][hh * 33 + k];
        out_avg[(size_t)(r0 + r) * TK + k] = sm * (1.f / NH);
        out_sel[(size_t)(r0 + r) * TK + k] = (float)g_sel[sets[r]][k];
    }
#pragma unroll 1
    for (int c = 0; c < 4; c++) {
        int o = c * 256 + tid;
        int h = o >> 6;
        float vv0[32], vv1[32];
#pragma unroll
        for (int k = 0; k < 32; k++) {
            vv0[k] = g_V[0][(size_t)k * DIM + o];
            vv1[k] = g_V[1][(size_t)k * DIM + o];
        }
#pragma unroll 1
        for (int r = 0; r < 16; r++) {
            const float* a = &att[r][h * 33];
            float sum = 0.f;
            if (sets[r]) {
#pragma unroll
                for (int k = 0; k < 32; k++) sum += a[k] * vv1[k];
            } else {
#pragma unroll
                for (int k = 0; k < 32; k++) sum += a[k] * vv0[k];
            }
            g_ctx[(size_t)(r0 + r) * DIM + o] = sum;
        }
    }
}

// ================= 8) LayerNorm =================
__global__ void __launch_bounds__(256) ln_kernel(const float* __restrict__ X,
                                                 const float* __restrict__ gamma,
                                                 const float* __restrict__ beta,
                                                 float* __restrict__ out) {
    int row = blockIdx.x;
    __shared__ float red[256];
    int t = threadIdx.x;
    const float* p = X + (size_t)row * DIM;
    float4 v = ((const float4*)p)[t];
    float s = v.x + v.y + v.z + v.w;
    red[t] = s; __syncthreads();
    for (int off = 128; off; off >>= 1) { if (t < off) red[t] += red[t + off]; __syncthreads(); }
    float mu = red[0] * (1.f / DIM);
    __syncthreads();
    float d0 = v.x - mu, d1 = v.y - mu, d2 = v.z - mu, d3 = v.w - mu;
    red[t] = d0 * d0 + d1 * d1 + d2 * d2 + d3 * d3;
    __syncthreads();
    for (int off = 128; off; off >>= 1) { if (t < off) red[t] += red[t + off]; __syncthreads(); }
    float inv = rsqrtf(red[0] * (1.f / DIM) + 1e-5f);
    float4 g = ((const float4*)gamma)[t];
    float4 b = ((const float4*)beta)[t];
    float4 o;
    o.x = d0 * inv * g.x + b.x;
    o.y = d1 * inv * g.y + b.y;
    o.z = d2 * inv * g.z + b.z;
    o.w = d3 * inv * g.w + b.w;
    ((float4*)(out + (size_t)row * DIM))[t] = o;
}

// ================= launch =================
extern "C" void kernel_launch(void* const* d_in, const int* in_sizes, int n_in,
                              void* d_out, int out_size) {
    const float* q    = (const float*)d_in[0];
    const float* mk   = (const float*)d_in[1];
    const float* mv   = (const float*)d_in[2];
    const float* Wq   = (const float*)d_in[3];
    const float* Wk   = (const float*)d_in[4];
    const float* Wv   = (const float*)d_in[5];
    const float* Wo   = (const float*)d_in[6];
    const float* bo   = (const float*)d_in[7];
    const float* gamma = (const float*)d_in[8];
    const float* beta  = (const float*)d_in[9];
    float* out = (float*)d_out;

    float *p_qfull, *p_ctx;
    __nv_bfloat16 *p_Ahi, *p_Alo, *p_Wqhi, *p_Wqlo, *p_Wohi, *p_Wolo;
    cudaGetSymbolAddress((void**)&p_qfull, g_qfull);
    cudaGetSymbolAddress((void**)&p_ctx, g_ctx);
    cudaGetSymbolAddress((void**)&p_Ahi, g_Ahi);
    cudaGetSymbolAddress((void**)&p_Alo, g_Alo);
    cudaGetSymbolAddress((void**)&p_Wqhi, g_Wqhi);
    cudaGetSymbolAddress((void**)&p_Wqlo, g_Wqlo);
    cudaGetSymbolAddress((void**)&p_Wohi, g_Wohi);
    cudaGetSymbolAddress((void**)&p_Wolo, g_Wolo);

    float* out_main = out;
    float* out_avg  = out + (size_t)NROWS * DIM;
    float* out_sel  = out + (size_t)NROWS * DIM + (size_t)NROWS * TK;

    dim3 gq(DIM / 128, NROWS / 128);

    stats_kernel<<<MKEYS / 8, 256>>>(mk);
    conv_kernel<<<NROWS * DIM / 4 / 256, 256>>>(q, p_Ahi, p_Alo, NROWS * DIM / 4);
    conv_kernel<<<DIM * DIM / 4 / 256, 256>>>(Wq, p_Wqhi, p_Wqlo, DIM * DIM / 4);
    conv_kernel<<<DIM * DIM / 4 / 256, 256>>>(Wo, p_Wohi, p_Wolo, DIM * DIM / 4);
    mma_gemm<<<gq, 256>>>(p_Ahi, p_Alo, p_Wqhi, p_Wqlo, p_qfull, nullptr);
    qm_kernel<<<NROWS, 256>>>();
    topk_part<<<dim3(16, 2), 1024>>>();
    topk_merge<<<2, 512>>>();
    selproj_kernel<<<dim3(DIM / 64, 4), 256>>>(mk, mv, Wk, Wv);
    attn_scores<<<dim3(NH, NROWS / 64), 256>>>();
    attn_ctx<<<NROWS / 16, 256>>>(out_avg, out_sel);
    conv_kernel<<<NROWS * DIM / 4 / 256, 256>>>(p_ctx, p_Ahi, p_Alo, NROWS * DIM / 4);
    mma_gemm<<<gq, 256>>>(p_Ahi, p_Alo, p_Wohi, p_Wolo, p_qfull, bo);
    ln_kernel<<<NROWS, 256>>>(p_qfull, gamma, beta, out_main);
    (void)in_sizes; (void)n_in; (void)out_size;
}

// round 8
// speedup vs baseline: 3.5429x; 1.1704x over previous
#include <cuda_runtime.h>
#include <cuda_bf16.h>
#include <math.h>
#include <stdint.h>

// Problem constants
#define NROWS 2048      // B*N
#define DIM   1024      // D
#define MKEYS 32768     // M
#define TK    32        // top-k
#define NH    16        // heads
#define HDIM  64        // head dim

// ================= scratch (device globals) =================
__device__ float g_qfull[NROWS * DIM];   // q_proj output; reused as pre-LN out
__device__ float g_ctx[NROWS * DIM];     // attention context
__device__ int   g_set[NROWS];           // per-row set selector (sign of qm)
__device__ float g_c[MKEYS];             // c_m
__device__ int   g_sel[2][TK];
__device__ float g_Kt[2][DIM * TK];      // projected keys, transposed [o][k]
__device__ float g_V[2][TK * DIM];       // projected values [k][o]
__device__ float g_att[NROWS * (NH * TK)];
__device__ unsigned long long g_part[2][16][TK];
__device__ float g_qmp[8 * NROWS];       // per-coltile partial row sums of q_full

// ================= PTX helpers (sm_80+ features only) =================
__device__ __forceinline__ uint32_t smem_u32(const void* p) {
    uint32_t a;
    asm("{ .reg .u64 t; cvta.to.shared.u64 t, %1; cvt.u32.u64 %0, t; }" : "=r"(a) : "l"(p));
    return a;
}
__device__ __forceinline__ void ldsm4(uint32_t* r, uint32_t addr) {
    asm volatile("ldmatrix.sync.aligned.m8n8.x4.shared.b16 {%0,%1,%2,%3}, [%4];"
        : "=r"(r[0]), "=r"(r[1]), "=r"(r[2]), "=r"(r[3]) : "r"(addr));
}
__device__ __forceinline__ void mma16816(float* c, const uint32_t* a, const uint32_t* b) {
    asm volatile("mma.sync.aligned.m16n8k16.row.col.f32.bf16.bf16.f32 "
        "{%0,%1,%2,%3}, {%4,%5,%6,%7}, {%8,%9}, {%0,%1,%2,%3};"
        : "+f"(c[0]), "+f"(c[1]), "+f"(c[2]), "+f"(c[3])
        : "r"(a[0]), "r"(a[1]), "r"(a[2]), "r"(a[3]), "r"(b[0]), "r"(b[1]));
}
// pack (lo,hi) floats into bf16x2 (lo in low half)
__device__ __forceinline__ uint32_t cvt_bf2(float lo, float hi) {
    uint32_t r;
    asm("cvt.rn.bf16x2.f32 %0, %1, %2;" : "=r"(r) : "f"(hi), "f"(lo));
    return r;
}

// ================= 1) per-memory-row stats =================
__global__ void stats_kernel(const float* __restrict__ keys) {
    int warp = (blockIdx.x * blockDim.x + threadIdx.x) >> 5;
    int lane = threadIdx.x & 31;
    if (warp >= MKEYS) return;
    const float4* p = (const float4*)(keys + (size_t)warp * DIM);
    float s = 0.f, sq = 0.f;
#pragma unroll
    for (int i = 0; i < 8; i++) {
        float4 v = p[lane + i * 32];
        s  += v.x + v.y + v.z + v.w;
        sq += v.x * v.x + v.y * v.y + v.z * v.z + v.w * v.w;
    }
#pragma unroll
    for (int o = 16; o; o >>= 1) {
        s  += __shfl_xor_sync(0xffffffffu, s, o);
        sq += __shfl_xor_sync(0xffffffffu, sq, o);
    }
    if (lane == 0) g_c[warp] = s / (32.0f * sqrtf(sq));
}

// ================= 2) top-32 =================
__device__ __forceinline__ unsigned long long tk_make_key(float f, int m) {
    unsigned b = __float_as_uint(f);
    unsigned k = (b & 0x80000000u) ? ~b : (b | 0x80000000u);
    return ((unsigned long long)k << 32) | (unsigned long long)(0xFFFFFFFFu - (unsigned)m);
}
__device__ __forceinline__ unsigned long long tk_sort_asc(unsigned long long v) {
    unsigned lane = threadIdx.x & 31;
#pragma unroll
    for (int k = 2; k <= 32; k <<= 1) {
#pragma unroll
        for (int j = k >> 1; j > 0; j >>= 1) {
            unsigned long long o = __shfl_xor_sync(0xffffffffu, v, j);
            bool up = ((lane & k) == 0), lower = ((lane & j) == 0);
            unsigned long long mn = v < o ? v : o, mx = v < o ? o : v;
            v = (up == lower) ? mn : mx;
        }
    }
    return v;
}
__device__ __forceinline__ unsigned long long tk_bmerge_asc(unsigned long long v) {
    unsigned lane = threadIdx.x & 31;
#pragma unroll
    for (int j = 16; j > 0; j >>= 1) {
        unsigned long long o = __shfl_xor_sync(0xffffffffu, v, j);
        unsigned long long mn = v < o ? v : o, mx = v < o ? o : v;
        v = ((lane & j) == 0) ? mn : mx;
    }
    return v;
}
__global__ void __launch_bounds__(1024) topk_part() {
    int set = blockIdx.y, p = blockIdx.x;
    int lane = threadIdx.x & 31, w = threadIdx.x >> 5;
    __shared__ unsigned long long sh[32][33];
    float sgn = set ? -1.f : 1.f;
    int base = p * 2048 + w * 64;
    int i0 = base + lane, i1 = base + 32 + lane;
    float f0 = sgn * g_c[i0], f1 = sgn * g_c[i1];
    unsigned long long a = tk_sort_asc(tk_make_key(f0, i0));
    unsigned long long b = tk_sort_asc(tk_make_key(f1, i1));
    unsigned long long o = __shfl_sync(0xffffffffu, b, 31 - lane);
    unsigned long long v = a > o ? a : o;
    a = tk_bmerge_asc(v);
    sh[w][lane] = a;
    __syncthreads();
#pragma unroll
    for (int st = 1; st < 32; st <<= 1) {
        if (w < 16 / st) {
            unsigned long long A = sh[2 * w * st][lane];
            unsigned long long B = sh[(2 * w + 1) * st][31 - lane];
            unsigned long long m = A > B ? A : B;
            m = tk_bmerge_asc(m);
            sh[2 * w * st][lane] = m;
        }
        __syncthreads();
    }
    if (w == 0) g_part[set][p][lane] = sh[0][lane];
}
__global__ void __launch_bounds__(512) topk_merge() {
    int set = blockIdx.x;
    int lane = threadIdx.x & 31, w = threadIdx.x >> 5;
    __shared__ unsigned long long sh[16][33];
    sh[w][lane] = g_part[set][w][lane];
    __syncthreads();
#pragma unroll
    for (int st = 1; st < 16; st <<= 1) {
        if (w < 8 / st) {
            unsigned long long A = sh[2 * w * st][lane];
            unsigned long long B = sh[(2 * w + 1) * st][31 - lane];
            unsigned long long m = A > B ? A : B;
            m = tk_bmerge_asc(m);
            sh[2 * w * st][lane] = m;
        }
        __syncthreads();
    }
    if (w == 0) {
        unsigned long long v = sh[0][lane];
        int m = (int)(0xFFFFFFFFu - (unsigned)(v & 0xFFFFFFFFull));
        g_sel[set][31 - lane] = m;
    }
}

// ================= 3) HMMA bf16x3 GEMM with fused fp32->hi/lo split =================
// C[2048,1024] = A[*,1024] * B[1024,1024]^T (+bias); optional row-sum partials.
// 128x128 CTA tile, BK=32, 8 warps (2x4), warp tile 64x32
#define BK 32
#define NK (DIM / BK)
#define SSTRIDE 40   // bf16 elems per smem row (80B; conflict-free ldmatrix)

__global__ void __launch_bounds__(256) mma_gemm(
    const float* __restrict__ A, const float* __restrict__ B,
    float* __restrict__ C, const float* __restrict__ bias,
    float* __restrict__ qmp) {
    __shared__ __align__(16) __nv_bfloat16 sm[4][128 * SSTRIDE];  // Ahi, Alo, Bhi, Blo
    __shared__ float sq[4][128];
    int tid = threadIdx.x, lane = tid & 31, wid = tid >> 5;
    int bm = blockIdx.y * 128, bn = blockIdx.x * 128;
    int wm = wid >> 2, wn = wid & 3;
    int m0 = wm * 64, n0 = wn * 32;

    const float* srcs[2] = { A + (size_t)bm * DIM, B + (size_t)bn * DIM };

    uint32_t sbase[4];
#pragma unroll
    for (int t = 0; t < 4; t++) sbase[t] = smem_u32(sm[t]);

    int a_ro = (m0 + (lane & 15)) * SSTRIDE + ((lane & 16) ? 8 : 0);
    int b_ro = (n0 + (lane & 7) + ((lane & 16) ? 8 : 0)) * SSTRIDE + ((lane & 8) ? 8 : 0);

    float acc[4][4][4];
#pragma unroll
    for (int i = 0; i < 4; i++)
#pragma unroll
        for (int j = 0; j < 4; j++)
#pragma unroll
            for (int r = 0; r < 4; r++) acc[i][j][r] = 0.f;

    // prefetch registers: 2 matrices x 4 float4 per thread (tile = 128 rows x 32 fp32)
    float4 pf[8];
#pragma unroll
    for (int t = 0; t < 2; t++)
#pragma unroll
        for (int u = 0; u < 4; u++) {
            int c = tid + u * 256, row = c >> 3, fc = c & 7;
            pf[t * 4 + u] = *(const float4*)(srcs[t] + (size_t)row * DIM + fc * 4);
        }

#pragma unroll 1
    for (int kt = 0; kt < NK; kt++) {
        // convert + store to hi/lo smem
#pragma unroll
        for (int t = 0; t < 2; t++)
#pragma unroll
            for (int u = 0; u < 4; u++) {
                int c = tid + u * 256, row = c >> 3, fc = c & 7;
                float4 v = pf[t * 4 + u];
                uint32_t h01 = cvt_bf2(v.x, v.y);
                uint32_t h23 = cvt_bf2(v.z, v.w);
                float l0 = v.x - __uint_as_float(h01 << 16);
                float l1 = v.y - __uint_as_float(h01 & 0xFFFF0000u);
                float l2 = v.z - __uint_as_float(h23 << 16);
                float l3 = v.w - __uint_as_float(h23 & 0xFFFF0000u);
                uint32_t l01 = cvt_bf2(l0, l1);
                uint32_t l23 = cvt_bf2(l2, l3);
                uint2 hv = make_uint2(h01, h23), lv = make_uint2(l01, l23);
                *(uint2*)(&sm[t * 2][row * SSTRIDE + fc * 4]) = hv;
                *(uint2*)(&sm[t * 2 + 1][row * SSTRIDE + fc * 4]) = lv;
            }
        __syncthreads();
        if (kt + 1 < NK) {
#pragma unroll
            for (int t = 0; t < 2; t++)
#pragma unroll
                for (int u = 0; u < 4; u++) {
                    int c = tid + u * 256, row = c >> 3, fc = c & 7;
                    pf[t * 4 + u] = *(const float4*)(srcs[t] + (size_t)row * DIM + (kt + 1) * BK + fc * 4);
                }
        }
#pragma unroll
        for (int ks = 0; ks < 2; ks++) {
            uint32_t ah[4][4], al[4][4];
#pragma unroll
            for (int mt = 0; mt < 4; mt++) {
                uint32_t off = 2u * (uint32_t)(a_ro + mt * 16 * SSTRIDE + ks * 16);
                ldsm4(ah[mt], sbase[0] + off);
                ldsm4(al[mt], sbase[1] + off);
            }
            uint32_t bh[4][2], bl[4][2];
#pragma unroll
            for (int pr = 0; pr < 2; pr++) {
                uint32_t off = 2u * (uint32_t)(b_ro + pr * 16 * SSTRIDE + ks * 16);
                uint32_t r[4];
                ldsm4(r, sbase[2] + off);
                bh[pr * 2][0] = r[0]; bh[pr * 2][1] = r[1];
                bh[pr * 2 + 1][0] = r[2]; bh[pr * 2 + 1][1] = r[3];
                ldsm4(r, sbase[3] + off);
                bl[pr * 2][0] = r[0]; bl[pr * 2][1] = r[1];
                bl[pr * 2 + 1][0] = r[2]; bl[pr * 2 + 1][1] = r[3];
            }
#pragma unroll
            for (int mt = 0; mt < 4; mt++)
#pragma unroll
                for (int nt = 0; nt < 4; nt++) {
                    mma16816(acc[mt][nt], ah[mt], bh[nt]);
                    mma16816(acc[mt][nt], ah[mt], bl[nt]);
                    mma16816(acc[mt][nt], al[mt], bh[nt]);
                }
        }
        __syncthreads();
    }

    int gid = lane >> 2, tig = lane & 3;
#pragma unroll
    for (int mt = 0; mt < 4; mt++)
#pragma unroll
        for (int nt = 0; nt < 4; nt++) {
            int row = bm + m0 + mt * 16 + gid;
            int col = bn + n0 + nt * 8 + tig * 2;
            float b0 = 0.f, b1 = 0.f;
            if (bias) { b0 = bias[col]; b1 = bias[col + 1]; }
            float2 v0 = make_float2(acc[mt][nt][0] + b0, acc[mt][nt][1] + b1);
            float2 v1 = make_float2(acc[mt][nt][2] + b0, acc[mt][nt][3] + b1);
            *(float2*)(C + (size_t)row * DIM + col) = v0;
            *(float2*)(C + (size_t)(row + 8) * DIM + col) = v1;
        }

    if (qmp) {   // deterministic per-CTA row-sum partials (for qm sign)
#pragma unroll
        for (int mt = 0; mt < 4; mt++) {
            float p0 = 0.f, p1 = 0.f;
#pragma unroll
            for (int nt = 0; nt < 4; nt++) {
                p0 += acc[mt][nt][0] + acc[mt][nt][1];
                p1 += acc[mt][nt][2] + acc[mt][nt][3];
            }
            p0 += __shfl_xor_sync(0xffffffffu, p0, 1);
            p0 += __shfl_xor_sync(0xffffffffu, p0, 2);
            p1 += __shfl_xor_sync(0xffffffffu, p1, 1);
            p1 += __shfl_xor_sync(0xffffffffu, p1, 2);
            if (tig == 0) {
                sq[wn][m0 + mt * 16 + gid] = p0;
                sq[wn][m0 + mt * 16 + gid + 8] = p1;
            }
        }
        __syncthreads();
        if (tid < 128) {
            float s = sq[0][tid] + sq[1][tid] + sq[2][tid] + sq[3][tid];
            qmp[(size_t)blockIdx.x * NROWS + bm + tid] = s;
        }
    }
}

// ================= 4) qm sign from partials =================
__global__ void __launch_bounds__(256) qm_kernel() {
    int row = blockIdx.x * 256 + threadIdx.x;
    float s = 0.f;
#pragma unroll
    for (int j = 0; j < 8; j++) s += g_qmp[(size_t)j * NROWS + row];
    g_set[row] = (s >= 0.f) ? 0 : 1;
}

// ================= 5) project selected K/V =================
__global__ void __launch_bounds__(256) selproj_kernel(const float* __restrict__ keys,
                                                      const float* __restrict__ vals,
                                                      const float* __restrict__ Wk,
                                                      const float* __restrict__ Wv) {
    int set = blockIdx.y >> 1, kv = blockIdx.y & 1;
    const float* S = kv ? vals : keys;
    const float* W = kv ? Wv : Wk;
    __shared__ float Ss[32][33];
    __shared__ float Ws[64][33];
    __shared__ int sel[32];
    int t = threadIdx.x;
    if (t < 32) sel[t] = g_sel[set][t];
    __syncthreads();
    int olocal = t & 63;
    int kbase = (t >> 6) * 8;
    int obase = blockIdx.x * 64;
    float acc[8];
#pragma unroll
    for (int i = 0; i < 8; i++) acc[i] = 0.f;

    for (int dc = 0; dc < DIM; dc += 32) {
        {
            int idx = t * 4; int r = idx >> 5; int c = idx & 31;
            float4 v = *(const float4*)(S + (size_t)sel[r] * DIM + dc + c);
            Ss[r][c] = v.x; Ss[r][c + 1] = v.y; Ss[r][c + 2] = v.z; Ss[r][c + 3] = v.w;
        }
        {
#pragma unroll
            for (int u = 0; u < 2; u++) {
                int id = t * 8 + u * 4; int r = id >> 5; int c = id & 31;
                float4 v = *(const float4*)(W + (size_t)(obase + r) * DIM + dc + c);
                Ws[r][c] = v.x; Ws[r][c + 1] = v.y; Ws[r][c + 2] = v.z; Ws[r][c + 3] = v.w;
            }
        }
        __syncthreads();
#pragma unroll
        for (int dd = 0; dd < 32; dd++) {
            float w = Ws[olocal][dd];
#pragma unroll
            for (int kk = 0; kk < 8; kk++) acc[kk] += Ss[kbase + kk][dd] * w;
        }
        __syncthreads();
    }
#pragma unroll
    for (int kk = 0; kk < 8; kk++) {
        int k = kbase + kk, o = obase + olocal;
        if (kv == 0) g_Kt[set][(size_t)o * TK + k] = acc[kk];
        else         g_V[set][(size_t)k * DIM + o] = acc[kk];
    }
}

// ================= 6a) attention scores + softmax =================
__global__ void __launch_bounds__(256) attn_scores() {
    int h = blockIdx.x;
    int r0 = blockIdx.y * 64;
    __shared__ float qs[64][65];
    __shared__ float Ks[2][64][33];
    __shared__ int sets[64];
    int tid = threadIdx.x;
#pragma unroll
    for (int u = 0; u < 4; u++) {
        int c = tid + u * 256;
        int r = c >> 4, q4 = c & 15;
        float4 v = *(const float4*)(g_qfull + (size_t)(r0 + r) * DIM + h * HDIM + q4 * 4);
        qs[r][q4 * 4 + 0] = v.x; qs[r][q4 * 4 + 1] = v.y; qs[r][q4 * 4 + 2] = v.z; qs[r][q4 * 4 + 3] = v.w;
    }
#pragma unroll
    for (int u = 0; u < 4; u++) {
        int c = tid + u * 256;
        int s = c >> 9, rem = c & 511, j = rem >> 3, k4 = rem & 7;
        float4 v = *(const float4*)(&g_Kt[s][(size_t)(h * HDIM + j) * TK + k4 * 4]);
        Ks[s][j][k4 * 4 + 0] = v.x; Ks[s][j][k4 * 4 + 1] = v.y; Ks[s][j][k4 * 4 + 2] = v.z; Ks[s][j][k4 * 4 + 3] = v.w;
    }
    if (tid < 64) sets[tid] = g_set[r0 + tid];
    __syncthreads();
    int r = tid >> 2, kg = tid & 3;
    int s = sets[r];
    float sc[8];
#pragma unroll
    for (int kk = 0; kk < 8; kk++) sc[kk] = 0.f;
#pragma unroll
    for (int j = 0; j < 64; j++) {
        float qv = qs[r][j];
#pragma unroll
        for (int kk = 0; kk < 8; kk++) sc[kk] += qv * Ks[s][j][kg * 8 + kk];
    }
    float mx = -INFINITY;
#pragma unroll
    for (int kk = 0; kk < 8; kk++) { sc[kk] *= 0.125f; mx = fmaxf(mx, sc[kk]); }
#pragma unroll
    for (int o = 1; o <= 2; o <<= 1) mx = fmaxf(mx, __shfl_xor_sync(0xffffffffu, mx, o));
    float e[8]; float sum = 0.f;
#pragma unroll
    for (int kk = 0; kk < 8; kk++) { e[kk] = expf(sc[kk] - mx); sum += e[kk]; }
#pragma unroll
    for (int o = 1; o <= 2; o <<= 1) sum += __shfl_xor_sync(0xffffffffu, sum, o);
    float inv = 1.f / sum;
    float* dst = &g_att[(size_t)(r0 + r) * (NH * TK) + h * TK + kg * 8];
    *(float4*)(dst)     = make_float4(e[0] * inv, e[1] * inv, e[2] * inv, e[3] * inv);
    *(float4*)(dst + 4) = make_float4(e[4] * inv, e[5] * inv, e[6] * inv, e[7] * inv);
}

// ================= 6b) context + avg_attn + sel_idx =================
__global__ void __launch_bounds__(256) attn_ctx(float* __restrict__ out_avg,
                                                float* __restrict__ out_sel) {
    int r0 = blockIdx.x * 16;
    __shared__ float att[16][NH * 33];
    __shared__ int sets[16];
    int tid = threadIdx.x;
    if (tid < 16) sets[tid] = g_set[r0 + tid];
#pragma unroll
    for (int u = 0; u < 8; u++) {
        int c = tid + u * 256;
        int r = c >> 7, rem = c & 127;
        float4 v = *(const float4*)(&g_att[(size_t)(r0 + r) * (NH * TK) + rem * 4]);
        int hh = (rem * 4) >> 5, k = (rem * 4) & 31;
        float* d = &att[r][hh * 33 + k];
        d[0] = v.x; d[1] = v.y; d[2] = v.z; d[3] = v.w;
    }
    __syncthreads();
#pragma unroll
    for (int u = 0; u < 2; u++) {
        int c = tid + u * 256;
        int r = c >> 5, k = c & 31;
        float sm = 0.f;
#pragma unroll
        for (int hh = 0; hh < NH; hh++) sm += att[r][hh * 33 + k];
        out_avg[(size_t)(r0 + r) * TK + k] = sm * (1.f / NH);
        out_sel[(size_t)(r0 + r) * TK + k] = (float)g_sel[sets[r]][k];
    }
#pragma unroll 1
    for (int c = 0; c < 4; c++) {
        int o = c * 256 + tid;
        int h = o >> 6;
        float vv0[32], vv1[32];
#pragma unroll
        for (int k = 0; k < 32; k++) {
            vv0[k] = g_V[0][(size_t)k * DIM + o];
            vv1[k] = g_V[1][(size_t)k * DIM + o];
        }
#pragma unroll 1
        for (int r = 0; r < 16; r++) {
            const float* a = &att[r][h * 33];
            float sum = 0.f;
            if (sets[r]) {
#pragma unroll
                for (int k = 0; k < 32; k++) sum += a[k] * vv1[k];
            } else {
#pragma unroll
                for (int k = 0; k < 32; k++) sum += a[k] * vv0[k];
            }
            g_ctx[(size_t)(r0 + r) * DIM + o] = sum;
        }
    }
}

// ================= 7) LayerNorm =================
__global__ void __launch_bounds__(256) ln_kernel(const float* __restrict__ X,
                                                 const float* __restrict__ gamma,
                                                 const float* __restrict__ beta,
                                                 float* __restrict__ out) {
    int row = blockIdx.x;
    __shared__ float red[256];
    int t = threadIdx.x;
    const float* p = X + (size_t)row * DIM;
    float4 v = ((const float4*)p)[t];
    float s = v.x + v.y + v.z + v.w;
    red[t] = s; __syncthreads();
    for (int off = 128; off; off >>= 1) { if (t < off) red[t] += red[t + off]; __syncthreads(); }
    float mu = red[0] * (1.f / DIM);
    __syncthreads();
    float d0 = v.x - mu, d1 = v.y - mu, d2 = v.z - mu, d3 = v.w - mu;
    red[t] = d0 * d0 + d1 * d1 + d2 * d2 + d3 * d3;
    __syncthreads();
    for (int off = 128; off; off >>= 1) { if (t < off) red[t] += red[t + off]; __syncthreads(); }
    float inv = rsqrtf(red[0] * (1.f / DIM) + 1e-5f);
    float4 g = ((const float4*)gamma)[t];
    float4 b = ((const float4*)beta)[t];
    float4 o;
    o.x = d0 * inv * g.x + b.x;
    o.y = d1 * inv * g.y + b.y;
    o.z = d2 * inv * g.z + b.z;
    o.w = d3 * inv * g.w + b.w;
    ((float4*)(out + (size_t)row * DIM))[t] = o;
}

// ================= launch =================
extern "C" void kernel_launch(void* const* d_in, const int* in_sizes, int n_in,
                              void* d_out, int out_size) {
    const float* q    = (const float*)d_in[0];
    const float* mk   = (const float*)d_in[1];
    const float* mv   = (const float*)d_in[2];
    const float* Wq   = (const float*)d_in[3];
    const float* Wk   = (const float*)d_in[4];
    const float* Wv   = (const float*)d_in[5];
    const float* Wo   = (const float*)d_in[6];
    const float* bo   = (const float*)d_in[7];
    const float* gamma = (const float*)d_in[8];
    const float* beta  = (const float*)d_in[9];
    float* out = (float*)d_out;

    float *p_qfull, *p_ctx, *p_qmp;
    cudaGetSymbolAddress((void**)&p_qfull, g_qfull);
    cudaGetSymbolAddress((void**)&p_ctx, g_ctx);
    cudaGetSymbolAddress((void**)&p_qmp, g_qmp);

    float* out_main = out;
    float* out_avg  = out + (size_t)NROWS * DIM;
    float* out_sel  = out + (size_t)NROWS * DIM + (size_t)NROWS * TK;

    dim3 gq(DIM / 128, NROWS / 128);

    stats_kernel<<<MKEYS / 8, 256>>>(mk);
    mma_gemm<<<gq, 256>>>(q, Wq, p_qfull, nullptr, p_qmp);
    qm_kernel<<<NROWS / 256, 256>>>();
    topk_part<<<dim3(16, 2), 1024>>>();
    topk_merge<<<2, 512>>>();
    selproj_kernel<<<dim3(DIM / 64, 4), 256>>>(mk, mv, Wk, Wv);
    attn_scores<<<dim3(NH, NROWS / 64), 256>>>();
    attn_ctx<<<NROWS / 16, 256>>>(out_avg, out_sel);
    mma_gemm<<<gq, 256>>>(p_ctx, Wo, p_qfull, bo, nullptr);
    ln_kernel<<<NROWS, 256>>>(p_qfull, gamma, beta, out_main);
    (void)in_sizes; (void)n_in; (void)out_size;
}